// round 8
// baseline (speedup 1.0000x reference)
#include <cuda_runtime.h>
#include <cuda_bf16.h>
#include <math.h>
#include <stdint.h>

#define MAXB 8192
#define MAXH 1024
typedef __nv_bfloat16 bf16;

// Scratch (device globals — no allocation allowed)
__device__ bf16 g_cond_hi[(size_t)MAXB * 2 * MAXH];
__device__ bf16 g_cond_lo[(size_t)MAXB * 2 * MAXH];
__device__ bf16 g_Wk_hi[(size_t)MAXH * MAXH];
__device__ bf16 g_Wk_lo[(size_t)MAXH * MAXH];
__device__ bf16 g_Wq_hi[(size_t)2 * MAXH * MAXH];
__device__ bf16 g_Wq_lo[(size_t)2 * MAXH * MAXH];
__device__ bf16 g_Wt_hi[(size_t)MAXH * 2 * MAXH];   // Wt[h, i] = W'[i, h]
__device__ bf16 g_Wt_lo[(size_t)MAXH * 2 * MAXH];
__device__ bf16 g_WvT_hi[(size_t)MAXH * MAXH];
__device__ bf16 g_WvT_lo[(size_t)MAXH * MAXH];
__device__ bf16 g_u_hi[(size_t)MAXB * MAXH];
__device__ bf16 g_u_lo[(size_t)MAXB * MAXH];
__device__ float g_r[(size_t)MAXB * MAXH];
__device__ float g_cp[MAXH];
__device__ float g_pp[MAXH];

__device__ __forceinline__ uint32_t smem_u32(const void* p) {
    uint32_t a;
    asm("{ .reg .u64 t; cvta.to.shared.u64 t, %1; cvt.u32.u64 %0, t; }" : "=r"(a) : "l"(p));
    return a;
}
__device__ __forceinline__ void bf16_split(float v, bf16& h, bf16& l) {
    h = __float2bfloat16(v);
    l = __float2bfloat16(v - __bfloat162float(h));
}

#define MMA16816(d, a, b0, b1) \
    asm volatile("mma.sync.aligned.m16n8k16.row.col.f32.bf16.bf16.f32 " \
        "{%0,%1,%2,%3}, {%4,%5,%6,%7}, {%8,%9}, {%0,%1,%2,%3};" \
        : "+f"((d)[0]), "+f"((d)[1]), "+f"((d)[2]), "+f"((d)[3]) \
        : "r"((a)[0]), "r"((a)[1]), "r"((a)[2]), "r"((a)[3]), "r"(b0), "r"(b1))

#define LDSM4(r, a) \
    asm volatile("ldmatrix.sync.aligned.m8n8.x4.shared.b16 {%0,%1,%2,%3}, [%4];" \
        : "=r"((r)[0]), "=r"((r)[1]), "=r"((r)[2]), "=r"((r)[3]) : "r"(a))

#define CP_ASYNC16(sa, gp) \
    asm volatile("cp.async.cg.shared.global [%0], [%1], 16;" :: "r"(sa), "l"(gp) : "memory")
#define CP_COMMIT() asm volatile("cp.async.commit_group;" ::: "memory")

// ---------------------------------------------------------------------------
// prep: fold + split(Wk) + split(Wq) + transpose-split(Wv), region dispatch.
// ---------------------------------------------------------------------------
__global__ __launch_bounds__(256)
void prep_kernel(const float* __restrict__ Wk, const float* __restrict__ Wq,
                 const float* __restrict__ Wv,
                 const float* __restrict__ bq, const float* __restrict__ bp,
                 const float* __restrict__ Wp,
                 bf16* __restrict__ wkh, bf16* __restrict__ wkl,
                 bf16* __restrict__ wqh, bf16* __restrict__ wql,
                 bf16* __restrict__ vth, bf16* __restrict__ vtl,
                 float* __restrict__ cp, float* __restrict__ pp, int H) {
    __shared__ float t[32][33];
    const int bid = blockIdx.x, tid = threadIdx.x;
    const int foldB = (H * 32) / 256;
    const int wkB = (H * H) / 256;
    const int wqB = (2 * H * H) / 256;

    if (bid < foldB) {
        int gw = (bid * 256 + tid) >> 5;
        int lane = tid & 31;
        const float* row = Wk + (size_t)gw * H;
        float ac = 0.f, ap = 0.f;
        for (int k = lane * 4; k < H; k += 128) {
            float4 w  = *(const float4*)(row + k);
            float4 q  = *(const float4*)(bq + k);
            float4 p  = *(const float4*)(bp + k);
            float4 wp = *(const float4*)(Wp + k);
            ac += (q.x + p.x) * w.x + (q.y + p.y) * w.y + (q.z + p.z) * w.z + (q.w + p.w) * w.w;
            ap += wp.x * w.x + wp.y * w.y + wp.z * w.z + wp.w * w.w;
        }
        for (int o = 16; o; o >>= 1) {
            ac += __shfl_xor_sync(0xFFFFFFFFu, ac, o);
            ap += __shfl_xor_sync(0xFFFFFFFFu, ap, o);
        }
        if (lane == 0) { cp[gw] = ac; pp[gw] = ap; }
    } else if (bid < foldB + wkB) {
        int i = (bid - foldB) * 256 + tid;
        bf16 h, l; bf16_split(Wk[i], h, l);
        wkh[i] = h; wkl[i] = l;
    } else if (bid < foldB + wkB + wqB) {
        int i = (bid - foldB - wkB) * 256 + tid;
        bf16 h, l; bf16_split(Wq[i], h, l);
        wqh[i] = h; wql[i] = l;
    } else {
        int b2 = bid - foldB - wkB - wqB;
        int nbx = H / 32;
        int bx = b2 % nbx, by = b2 / nbx;
        int tx = tid & 31, ty = tid >> 5;   // ty 0..7
        int x = bx * 32 + tx;
        int y0 = by * 32;
        #pragma unroll
        for (int i = 0; i < 32; i += 8)
            t[ty + i][tx] = Wv[(size_t)(y0 + ty + i) * H + x];
        __syncthreads();
        int ox = y0 + tx;
        #pragma unroll
        for (int i = 0; i < 32; i += 8) {
            float v = t[tx][ty + i];
            bf16 h, l; bf16_split(v, h, l);
            size_t o = (size_t)(bx * 32 + ty + i) * H + ox;
            vth[o] = h; vtl[o] = l;
        }
    }
}

// ---------------------------------------------------------------------------
// pool: mean/max over S -> bf16 splits of cond [B, 2H]
// ---------------------------------------------------------------------------
__global__ void pool_kernel(const float* __restrict__ ES, bf16* __restrict__ ch,
                            bf16* __restrict__ cl, int B, int S, int H) {
    int idx = blockIdx.x * blockDim.x + threadIdx.x;
    if (idx >= B * H) return;
    int b = idx / H, h = idx - b * H;
    const float* p = ES + (size_t)b * S * H + h;
    float v = p[0], sum = v, mx = v;
    for (int s = 1; s < S; s++) { v = p[(size_t)s * H]; sum += v; mx = fmaxf(mx, v); }
    float mean = sum * (1.0f / (float)S);
    size_t o0 = (size_t)b * 2 * H + h, o1 = o0 + H;
    bf16 hh, ll;
    bf16_split(mean, hh, ll); ch[o0] = hh; cl[o0] = ll;
    bf16_split(mx,   hh, ll); ch[o1] = hh; cl[o1] = ll;
}

// ---------------------------------------------------------------------------
// bf16x3 tensor-core GEMM:  D[m,n] = sum_k A[m,k]*B[n,k]
// 128x128x32 tile, 256 thr (4x2 warps, 32x64 warp tile),
// 3-stage cp.async pipeline, ldmatrix fragment loads.
// EPI 0: bf16-split D -> (C0,C1) | 1: C0 = D + e0[n] + gate[m]*e1[n] | 2: C0 = D + e0[n]
// ---------------------------------------------------------------------------
#define SROW 40            // bf16 elems per smem row (32 data + 8 pad) = 80 B
#define ARR  (128 * SROW)  // elems per array (5120)
#define STG  (4 * ARR)     // elems per stage (20480)
#define NSTAGE 3

template<int EPI>
__global__ __launch_bounds__(256)
void mma_gemm(const bf16* __restrict__ Ah, const bf16* __restrict__ Al,
              const bf16* __restrict__ Bh, const bf16* __restrict__ Bl,
              void* __restrict__ C0v, void* __restrict__ C1v, int ldc, int K,
              const float* __restrict__ e0, const float* __restrict__ e1,
              const float* __restrict__ gate) {
    extern __shared__ bf16 sm[];
    const int tid = threadIdx.x;
    const int lane = tid & 31, wid = tid >> 5;
    const int warpM = wid >> 1, warpN = wid & 1;
    const int rowBase = blockIdx.y * 128, colBase = blockIdx.x * 128;
    const uint32_t smb = smem_u32(sm);

    float acc[2][8][4] = {};

    const bf16* srcs[4] = { Ah, Al, Bh, Bl };
    const int ldrow  = tid >> 2;           // 0..63
    const int ldrow2 = (tid + 256) >> 2;   // 64..127
    const int ldc16 = tid & 3;

    // ldmatrix lane-dependent offsets (elems)
    const int rA = lane & 15;
    const int cA = (lane >> 4) << 3;
    const int rB = (lane & 7) + ((lane >> 4) << 3);
    const int cB = ((lane >> 3) & 1) << 3;
    const uint32_t aoff0 = (uint32_t)((warpM * 32 + rA) * SROW + cA) * 2u;
    const uint32_t boff0 = (uint32_t)((warpN * 64 + rB) * SROW + cB) * 2u;

    #define LOAD_STAGE(s, k0) do {                                                   \
        _Pragma("unroll")                                                            \
        for (int a_ = 0; a_ < 4; a_++) {                                             \
            const bf16* src_ = srcs[a_];                                             \
            int base_ = (a_ < 2) ? rowBase : colBase;                                \
            uint32_t sa_ = smb + (uint32_t)((s) * STG + a_ * ARR) * 2u;              \
            const bf16* g1 = src_ + (size_t)(base_ + ldrow)  * K + (k0) + ldc16 * 8; \
            const bf16* g2 = src_ + (size_t)(base_ + ldrow2) * K + (k0) + ldc16 * 8; \
            CP_ASYNC16(sa_ + (uint32_t)(ldrow  * SROW + ldc16 * 8) * 2u, g1);        \
            CP_ASYNC16(sa_ + (uint32_t)(ldrow2 * SROW + ldc16 * 8) * 2u, g2);        \
        }                                                                            \
        CP_COMMIT();                                                                 \
    } while (0)

    const int nch = K >> 5;   // K / 32
    LOAD_STAGE(0, 0);
    LOAD_STAGE(1, 32);

    int s = 0;
    for (int c = 0; c < nch; c++) {
        if (c + 1 < nch) asm volatile("cp.async.wait_group 1;" ::: "memory");
        else             asm volatile("cp.async.wait_group 0;" ::: "memory");
        __syncthreads();

        // prefetch chunk c+2 into stage (c+2)%3 (the stage computed at c-1)
        if (c + 2 < nch) {
            int sn = s + 2; if (sn >= NSTAGE) sn -= NSTAGE;
            LOAD_STAGE(sn, (c + 2) * 32);
        }

        const uint32_t stb = smb + (uint32_t)(s * STG) * 2u;
        #pragma unroll
        for (int kk = 0; kk < 32; kk += 16) {
            uint32_t ah[2][4], al[2][4], bh[4][4], bl[4][4];
            #pragma unroll
            for (int mt = 0; mt < 2; mt++) {
                uint32_t off = aoff0 + (uint32_t)(mt * 16 * SROW + kk) * 2u;
                LDSM4(ah[mt], stb + off);
                LDSM4(al[mt], stb + (uint32_t)(ARR * 2) + off);
            }
            #pragma unroll
            for (int p = 0; p < 4; p++) {
                uint32_t off = boff0 + (uint32_t)(p * 16 * SROW + kk) * 2u;
                LDSM4(bh[p], stb + (uint32_t)(2 * ARR * 2) + off);
                LDSM4(bl[p], stb + (uint32_t)(3 * ARR * 2) + off);
            }
            #pragma unroll
            for (int p = 0; p < 4; p++)
            #pragma unroll
            for (int hf = 0; hf < 2; hf++) {
                int nt = p * 2 + hf;
                uint32_t b0h = bh[p][hf * 2], b1h = bh[p][hf * 2 + 1];
                uint32_t b0l = bl[p][hf * 2], b1l = bl[p][hf * 2 + 1];
                #pragma unroll
                for (int mt = 0; mt < 2; mt++) {
                    MMA16816(acc[mt][nt], ah[mt], b0h, b1h);
                    MMA16816(acc[mt][nt], ah[mt], b0l, b1l);
                    MMA16816(acc[mt][nt], al[mt], b0h, b1h);
                }
            }
        }
        if (++s >= NSTAGE) s = 0;
    }
    #undef LOAD_STAGE

    // ---- epilogue ----
    const int g = lane >> 2, tg = lane & 3;
    #pragma unroll
    for (int mt = 0; mt < 2; mt++) {
        int r0 = rowBase + warpM * 32 + mt * 16 + g;
        int r1 = r0 + 8;
        float g0 = 0.f, g1v = 0.f;
        if (EPI == 1) { g0 = gate[r0]; g1v = gate[r1]; }
        #pragma unroll
        for (int nt = 0; nt < 8; nt++) {
            int col = colBase + warpN * 64 + nt * 8 + tg * 2;
            float d0 = acc[mt][nt][0], d1 = acc[mt][nt][1];
            float d2 = acc[mt][nt][2], d3 = acc[mt][nt][3];
            if (EPI == 0) {
                bf16* C0 = (bf16*)C0v; bf16* C1 = (bf16*)C1v;
                bf16 h0, l0, h1, l1;
                bf16_split(d0, h0, l0); bf16_split(d1, h1, l1);
                *(__nv_bfloat162*)(C0 + (size_t)r0 * ldc + col) = __nv_bfloat162(h0, h1);
                *(__nv_bfloat162*)(C1 + (size_t)r0 * ldc + col) = __nv_bfloat162(l0, l1);
                bf16_split(d2, h0, l0); bf16_split(d3, h1, l1);
                *(__nv_bfloat162*)(C0 + (size_t)r1 * ldc + col) = __nv_bfloat162(h0, h1);
                *(__nv_bfloat162*)(C1 + (size_t)r1 * ldc + col) = __nv_bfloat162(l0, l1);
            } else {
                float* C0 = (float*)C0v;
                float a0 = e0[col], a1 = e0[col + 1];
                if (EPI == 1) {
                    float p0 = e1[col], p1 = e1[col + 1];
                    *(float2*)(C0 + (size_t)r0 * ldc + col) = make_float2(d0 + a0 + g0 * p0,  d1 + a1 + g0 * p1);
                    *(float2*)(C0 + (size_t)r1 * ldc + col) = make_float2(d2 + a0 + g1v * p0, d3 + a1 + g1v * p1);
                } else {
                    *(float2*)(C0 + (size_t)r0 * ldc + col) = make_float2(d0 + a0, d1 + a1);
                    *(float2*)(C0 + (size_t)r1 * ldc + col) = make_float2(d2 + a0, d3 + a1);
                }
            }
        }
    }
}

// ---------------------------------------------------------------------------
// attend: scores -> softmax -> weights/entropy; u (bf16 split)
// ---------------------------------------------------------------------------
__global__ __launch_bounds__(256)
void attend_kernel(const float* __restrict__ ES, const float* __restrict__ r,
                   const float* __restrict__ sbias,
                   float* __restrict__ w_out, float* __restrict__ ent_out,
                   bf16* __restrict__ uh_out, bf16* __restrict__ ul_out) {
    const int b = blockIdx.x;
    const int tid = threadIdx.x;
    __shared__ float es_sh[6 * 1024];
    __shared__ float red[6][8];

    const float4* src = (const float4*)(ES + (size_t)b * 6 * 1024);
    float4* dst = (float4*)es_sh;
    #pragma unroll
    for (int i = 0; i < 6; i++) dst[tid + i * 256] = src[tid + i * 256];
    float4 rv = ((const float4*)(r + (size_t)b * 1024))[tid];
    __syncthreads();

    float4 ev[6];
    float sc[6];
    #pragma unroll
    for (int s = 0; s < 6; s++) {
        ev[s] = *(const float4*)&es_sh[s * 1024 + tid * 4];
        sc[s] = ev[s].x * rv.x + ev[s].y * rv.y + ev[s].z * rv.z + ev[s].w * rv.w;
    }
    #pragma unroll
    for (int s = 0; s < 6; s++)
        for (int o = 16; o; o >>= 1) sc[s] += __shfl_xor_sync(0xFFFFFFFFu, sc[s], o);
    if ((tid & 31) == 0) {
        #pragma unroll
        for (int s = 0; s < 6; s++) red[s][tid >> 5] = sc[s];
    }
    __syncthreads();

    float w[6], m = -1e30f;
    #pragma unroll
    for (int s = 0; s < 6; s++) {
        float t = sbias[s];
        #pragma unroll
        for (int wp = 0; wp < 8; wp++) t += red[s][wp];
        w[s] = t; m = fmaxf(m, t);
    }
    float Z = 0.f;
    #pragma unroll
    for (int s = 0; s < 6; s++) { w[s] = expf(w[s] - m); Z += w[s]; }
    float inv = 1.f / Z, ent = 0.f;
    #pragma unroll
    for (int s = 0; s < 6; s++) { w[s] *= inv; ent -= w[s] * logf(w[s] + 1e-8f); }
    if (tid == 0) {
        #pragma unroll
        for (int s = 0; s < 6; s++) w_out[(size_t)b * 6 + s] = w[s];
        ent_out[b] = ent;
    }

    float4 u;
    u.x = w[0]*ev[0].x; u.y = w[0]*ev[0].y; u.z = w[0]*ev[0].z; u.w = w[0]*ev[0].w;
    #pragma unroll
    for (int s = 1; s < 6; s++) {
        u.x += w[s]*ev[s].x; u.y += w[s]*ev[s].y; u.z += w[s]*ev[s].z; u.w += w[s]*ev[s].w;
    }
    bf16 hx, lx, hy, ly, hz, lz, hw, lw;
    bf16_split(u.x, hx, lx); bf16_split(u.y, hy, ly);
    bf16_split(u.z, hz, lz); bf16_split(u.w, hw, lw);
    size_t o = (size_t)b * 1024 + tid * 4;
    *(__nv_bfloat162*)(uh_out + o)     = __nv_bfloat162(hx, hy);
    *(__nv_bfloat162*)(uh_out + o + 2) = __nv_bfloat162(hz, hw);
    *(__nv_bfloat162*)(ul_out + o)     = __nv_bfloat162(lx, ly);
    *(__nv_bfloat162*)(ul_out + o + 2) = __nv_bfloat162(lz, lw);
}

// ---------------------------------------------------------------------------
// Host
// ---------------------------------------------------------------------------
static const int GEMM_SMEM = NSTAGE * STG * 2;   // 122880 B

extern "C" void kernel_launch(void* const* d_in, const int* in_sizes, int n_in,
                              void* d_out, int out_size) {
    const float* ES    = (const float*)d_in[0];
    const float* gate  = (const float*)d_in[2];
    const float* Wk    = (const float*)d_in[3];
    const float* Wv    = (const float*)d_in[5];
    const float* bv    = (const float*)d_in[6];
    const float* Wq    = (const float*)d_in[7];
    const float* bq    = (const float*)d_in[8];
    const float* Wp    = (const float*)d_in[9];
    const float* bp    = (const float*)d_in[10];
    const float* sbias = (const float*)d_in[11];

    const int B = in_sizes[2];    // [B,1]
    const int H = in_sizes[4];    // [H]
    const int S = in_sizes[11];   // [S]

    float* out       = (float*)d_out;
    float* out_fused = out;
    float* out_w     = out + (size_t)B * H;
    float* out_ent   = out_w + (size_t)B * S;

    bf16 *ch, *cl, *wkh, *wkl, *wqh, *wql, *wth, *wtl, *vth, *vtl, *uh, *ul;
    float *rr, *cp, *pp;
    cudaGetSymbolAddress((void**)&ch,  g_cond_hi);
    cudaGetSymbolAddress((void**)&cl,  g_cond_lo);
    cudaGetSymbolAddress((void**)&wkh, g_Wk_hi);
    cudaGetSymbolAddress((void**)&wkl, g_Wk_lo);
    cudaGetSymbolAddress((void**)&wqh, g_Wq_hi);
    cudaGetSymbolAddress((void**)&wql, g_Wq_lo);
    cudaGetSymbolAddress((void**)&wth, g_Wt_hi);
    cudaGetSymbolAddress((void**)&wtl, g_Wt_lo);
    cudaGetSymbolAddress((void**)&vth, g_WvT_hi);
    cudaGetSymbolAddress((void**)&vtl, g_WvT_lo);
    cudaGetSymbolAddress((void**)&uh,  g_u_hi);
    cudaGetSymbolAddress((void**)&ul,  g_u_lo);
    cudaGetSymbolAddress((void**)&rr,  g_r);
    cudaGetSymbolAddress((void**)&cp,  g_cp);
    cudaGetSymbolAddress((void**)&pp,  g_pp);

    cudaFuncSetAttribute(mma_gemm<0>, cudaFuncAttributeMaxDynamicSharedMemorySize, GEMM_SMEM);
    cudaFuncSetAttribute(mma_gemm<1>, cudaFuncAttributeMaxDynamicSharedMemorySize, GEMM_SMEM);
    cudaFuncSetAttribute(mma_gemm<2>, cudaFuncAttributeMaxDynamicSharedMemorySize, GEMM_SMEM);

    // 0: prep (fold + weight splits + Wv transpose-split)
    {
        int grid = (H * 32) / 256 + (H * H) / 256 + (2 * H * H) / 256 + (H / 32) * (H / 32);
        prep_kernel<<<grid, 256>>>(Wk, Wq, Wv, bq, bp, Wp,
                                   wkh, wkl, wqh, wql, vth, vtl, cp, pp, H);
    }
    // 1: pools + cond split
    pool_kernel<<<(B * H + 255) / 256, 256>>>(ES, ch, cl, B, S, H);
    // 2: K1: Wt[m,n] = sum_j Wk[m,j]*Wq[n,j]  -> [H, 2H], split epilogue
    {
        dim3 grid((2 * H) / 128, H / 128);
        mma_gemm<0><<<grid, 256, GEMM_SMEM>>>(wkh, wkl, wqh, wql,
            wth, wtl, 2 * H, H, nullptr, nullptr, nullptr);
    }
    // 3: K2: r[b,h] = sum_i cond[b,i]*Wt[h,i] + cp[h] + gate[b]*pp[h]
    {
        dim3 grid(H / 128, B / 128);
        mma_gemm<1><<<grid, 256, GEMM_SMEM>>>(ch, cl, wth, wtl,
            rr, nullptr, H, 2 * H, cp, pp, gate);
    }
    // 4: attend (softmax/entropy + u split)
    attend_kernel<<<B, 256>>>(ES, rr, sbias, out_w, out_ent, uh, ul);
    // 5: K4: fused[b,j] = sum_h u[b,h]*WvT[j,h] + bv[j]
    {
        dim3 grid(H / 128, B / 128);
        mma_gemm<2><<<grid, 256, GEMM_SMEM>>>(uh, ul, vth, vtl,
            out_fused, nullptr, H, H, bv, nullptr, nullptr);
    }
}

// round 9
// speedup vs baseline: 1.1154x; 1.1154x over previous
#include <cuda_runtime.h>
#include <cuda_bf16.h>
#include <math.h>
#include <stdint.h>

#define MAXB 8192
#define MAXH 1024
typedef __nv_bfloat16 bf16;

// Scratch (device globals — no allocation allowed)
__device__ bf16 g_cond_hi[(size_t)MAXB * 2 * MAXH];
__device__ bf16 g_cond_lo[(size_t)MAXB * 2 * MAXH];
__device__ bf16 g_Wk_hi[(size_t)MAXH * MAXH];
__device__ bf16 g_Wk_lo[(size_t)MAXH * MAXH];
__device__ bf16 g_Wq_hi[(size_t)2 * MAXH * MAXH];
__device__ bf16 g_Wq_lo[(size_t)2 * MAXH * MAXH];
__device__ bf16 g_Wt_hi[(size_t)MAXH * 2 * MAXH];   // Wt[h, i] = W'[i, h]
__device__ bf16 g_Wt_lo[(size_t)MAXH * 2 * MAXH];
__device__ bf16 g_WvT_hi[(size_t)MAXH * MAXH];
__device__ bf16 g_WvT_lo[(size_t)MAXH * MAXH];
__device__ bf16 g_u_hi[(size_t)MAXB * MAXH];
__device__ bf16 g_u_lo[(size_t)MAXB * MAXH];
__device__ float g_r[(size_t)MAXB * MAXH];
__device__ float g_cp[MAXH];
__device__ float g_pp[MAXH];

__device__ __forceinline__ uint32_t smem_u32(const void* p) {
    uint32_t a;
    asm("{ .reg .u64 t; cvta.to.shared.u64 t, %1; cvt.u32.u64 %0, t; }" : "=r"(a) : "l"(p));
    return a;
}
__device__ __forceinline__ void bf16_split(float v, bf16& h, bf16& l) {
    h = __float2bfloat16(v);
    l = __float2bfloat16(v - __bfloat162float(h));
}

#define MMA16816(d, a, b0, b1) \
    asm volatile("mma.sync.aligned.m16n8k16.row.col.f32.bf16.bf16.f32 " \
        "{%0,%1,%2,%3}, {%4,%5,%6,%7}, {%8,%9}, {%0,%1,%2,%3};" \
        : "+f"((d)[0]), "+f"((d)[1]), "+f"((d)[2]), "+f"((d)[3]) \
        : "r"((a)[0]), "r"((a)[1]), "r"((a)[2]), "r"((a)[3]), "r"(b0), "r"(b1))

#define LDSM4(r, a) \
    asm volatile("ldmatrix.sync.aligned.m8n8.x4.shared.b16 {%0,%1,%2,%3}, [%4];" \
        : "=r"((r)[0]), "=r"((r)[1]), "=r"((r)[2]), "=r"((r)[3]) : "r"(a))

#define CP_ASYNC16(sa, gp) \
    asm volatile("cp.async.cg.shared.global [%0], [%1], 16;" :: "r"(sa), "l"(gp) : "memory")
#define CP_COMMIT() asm volatile("cp.async.commit_group;" ::: "memory")

// ---------------------------------------------------------------------------
// prep: fold + split(Wk) + split(Wq) + transpose-split(Wv), region dispatch.
// ---------------------------------------------------------------------------
__global__ __launch_bounds__(256)
void prep_kernel(const float* __restrict__ Wk, const float* __restrict__ Wq,
                 const float* __restrict__ Wv,
                 const float* __restrict__ bq, const float* __restrict__ bp,
                 const float* __restrict__ Wp,
                 bf16* __restrict__ wkh, bf16* __restrict__ wkl,
                 bf16* __restrict__ wqh, bf16* __restrict__ wql,
                 bf16* __restrict__ vth, bf16* __restrict__ vtl,
                 float* __restrict__ cp, float* __restrict__ pp, int H) {
    __shared__ float t[32][33];
    const int bid = blockIdx.x, tid = threadIdx.x;
    const int foldB = (H * 32) / 256;
    const int wkB = (H * H) / 256;
    const int wqB = (2 * H * H) / 256;

    if (bid < foldB) {
        int gw = (bid * 256 + tid) >> 5;
        int lane = tid & 31;
        const float* row = Wk + (size_t)gw * H;
        float ac = 0.f, ap = 0.f;
        for (int k = lane * 4; k < H; k += 128) {
            float4 w  = *(const float4*)(row + k);
            float4 q  = *(const float4*)(bq + k);
            float4 p  = *(const float4*)(bp + k);
            float4 wp = *(const float4*)(Wp + k);
            ac += (q.x + p.x) * w.x + (q.y + p.y) * w.y + (q.z + p.z) * w.z + (q.w + p.w) * w.w;
            ap += wp.x * w.x + wp.y * w.y + wp.z * w.z + wp.w * w.w;
        }
        for (int o = 16; o; o >>= 1) {
            ac += __shfl_xor_sync(0xFFFFFFFFu, ac, o);
            ap += __shfl_xor_sync(0xFFFFFFFFu, ap, o);
        }
        if (lane == 0) { cp[gw] = ac; pp[gw] = ap; }
    } else if (bid < foldB + wkB) {
        int i = (bid - foldB) * 256 + tid;
        bf16 h, l; bf16_split(Wk[i], h, l);
        wkh[i] = h; wkl[i] = l;
    } else if (bid < foldB + wkB + wqB) {
        int i = (bid - foldB - wkB) * 256 + tid;
        bf16 h, l; bf16_split(Wq[i], h, l);
        wqh[i] = h; wql[i] = l;
    } else {
        int b2 = bid - foldB - wkB - wqB;
        int nbx = H / 32;
        int bx = b2 % nbx, by = b2 / nbx;
        int tx = tid & 31, ty = tid >> 5;   // ty 0..7
        int x = bx * 32 + tx;
        int y0 = by * 32;
        #pragma unroll
        for (int i = 0; i < 32; i += 8)
            t[ty + i][tx] = Wv[(size_t)(y0 + ty + i) * H + x];
        __syncthreads();
        int ox = y0 + tx;
        #pragma unroll
        for (int i = 0; i < 32; i += 8) {
            float v = t[tx][ty + i];
            bf16 h, l; bf16_split(v, h, l);
            size_t o = (size_t)(bx * 32 + ty + i) * H + ox;
            vth[o] = h; vtl[o] = l;
        }
    }
}

// ---------------------------------------------------------------------------
// pool: mean/max over S -> bf16 splits of cond [B, 2H]
// ---------------------------------------------------------------------------
__global__ void pool_kernel(const float* __restrict__ ES, bf16* __restrict__ ch,
                            bf16* __restrict__ cl, int B, int S, int H) {
    int idx = blockIdx.x * blockDim.x + threadIdx.x;
    if (idx >= B * H) return;
    int b = idx / H, h = idx - b * H;
    const float* p = ES + (size_t)b * S * H + h;
    float v = p[0], sum = v, mx = v;
    for (int s = 1; s < S; s++) { v = p[(size_t)s * H]; sum += v; mx = fmaxf(mx, v); }
    float mean = sum * (1.0f / (float)S);
    size_t o0 = (size_t)b * 2 * H + h, o1 = o0 + H;
    bf16 hh, ll;
    bf16_split(mean, hh, ll); ch[o0] = hh; cl[o0] = ll;
    bf16_split(mx,   hh, ll); ch[o1] = hh; cl[o1] = ll;
}

// ---------------------------------------------------------------------------
// bf16x3 tensor-core GEMM:  D[m,n] = sum_k A[m,k]*B[n,k]
// 128x128x32 tile, 256 thr (4x2 warps, 32x64 warp tile),
// 2-stage cp.async pipeline (80 KB smem -> 2 CTAs/SM), ldmatrix loads.
// EPI 0: bf16-split D -> (C0,C1) | 1: C0 = D + e0[n] + gate[m]*e1[n] | 2: C0 = D + e0[n]
// ---------------------------------------------------------------------------
#define SROW 40            // bf16 elems per smem row (32 data + 8 pad) = 80 B
#define ARR  (128 * SROW)  // elems per array (5120)
#define STG  (4 * ARR)     // elems per stage (20480)
#define NSTAGE 2

template<int EPI>
__global__ __launch_bounds__(256, 2)
void mma_gemm(const bf16* __restrict__ Ah, const bf16* __restrict__ Al,
              const bf16* __restrict__ Bh, const bf16* __restrict__ Bl,
              void* __restrict__ C0v, void* __restrict__ C1v, int ldc, int K,
              const float* __restrict__ e0, const float* __restrict__ e1,
              const float* __restrict__ gate) {
    extern __shared__ bf16 sm[];
    const int tid = threadIdx.x;
    const int lane = tid & 31, wid = tid >> 5;
    const int warpM = wid >> 1, warpN = wid & 1;
    const int rowBase = blockIdx.y * 128, colBase = blockIdx.x * 128;
    const uint32_t smb = smem_u32(sm);

    float acc[2][8][4] = {};

    const bf16* srcs[4] = { Ah, Al, Bh, Bl };
    const int ldrow  = tid >> 2;           // 0..63
    const int ldrow2 = (tid + 256) >> 2;   // 64..127
    const int ldc16 = tid & 3;

    // ldmatrix lane-dependent offsets (elems)
    const int rA = lane & 15;
    const int cA = (lane >> 4) << 3;
    const int rB = (lane & 7) + ((lane >> 4) << 3);
    const int cB = ((lane >> 3) & 1) << 3;
    const uint32_t aoff0 = (uint32_t)((warpM * 32 + rA) * SROW + cA) * 2u;
    const uint32_t boff0 = (uint32_t)((warpN * 64 + rB) * SROW + cB) * 2u;

    #define LOAD_STAGE(s, k0) do {                                                   \
        _Pragma("unroll")                                                            \
        for (int a_ = 0; a_ < 4; a_++) {                                             \
            const bf16* src_ = srcs[a_];                                             \
            int base_ = (a_ < 2) ? rowBase : colBase;                                \
            uint32_t sa_ = smb + (uint32_t)((s) * STG + a_ * ARR) * 2u;              \
            const bf16* g1 = src_ + (size_t)(base_ + ldrow)  * K + (k0) + ldc16 * 8; \
            const bf16* g2 = src_ + (size_t)(base_ + ldrow2) * K + (k0) + ldc16 * 8; \
            CP_ASYNC16(sa_ + (uint32_t)(ldrow  * SROW + ldc16 * 8) * 2u, g1);        \
            CP_ASYNC16(sa_ + (uint32_t)(ldrow2 * SROW + ldc16 * 8) * 2u, g2);        \
        }                                                                            \
        CP_COMMIT();                                                                 \
    } while (0)

    const int nch = K >> 5;   // K / 32
    LOAD_STAGE(0, 0);
    LOAD_STAGE(1, 32);

    for (int c = 0; c < nch; c++) {
        const int s = c & 1;
        if (c + 1 < nch) asm volatile("cp.async.wait_group 1;" ::: "memory");
        else             asm volatile("cp.async.wait_group 0;" ::: "memory");
        __syncthreads();

        const uint32_t stb = smb + (uint32_t)(s * STG) * 2u;
        #pragma unroll
        for (int kk = 0; kk < 32; kk += 16) {
            uint32_t ah[2][4], al[2][4];
            #pragma unroll
            for (int mt = 0; mt < 2; mt++) {
                uint32_t off = aoff0 + (uint32_t)(mt * 16 * SROW + kk) * 2u;
                LDSM4(ah[mt], stb + off);
                LDSM4(al[mt], stb + (uint32_t)(ARR * 2) + off);
            }
            #pragma unroll
            for (int p = 0; p < 4; p++) {
                uint32_t bh4[4], bl4[4];
                uint32_t off = boff0 + (uint32_t)(p * 16 * SROW + kk) * 2u;
                LDSM4(bh4, stb + (uint32_t)(2 * ARR * 2) + off);
                LDSM4(bl4, stb + (uint32_t)(3 * ARR * 2) + off);
                #pragma unroll
                for (int hf = 0; hf < 2; hf++) {
                    int nt = p * 2 + hf;
                    uint32_t b0h = bh4[hf * 2], b1h = bh4[hf * 2 + 1];
                    uint32_t b0l = bl4[hf * 2], b1l = bl4[hf * 2 + 1];
                    #pragma unroll
                    for (int mt = 0; mt < 2; mt++) {
                        MMA16816(acc[mt][nt], ah[mt], b0h, b1h);
                        MMA16816(acc[mt][nt], ah[mt], b0l, b1l);
                        MMA16816(acc[mt][nt], al[mt], b0h, b1h);
                    }
                }
            }
        }
        __syncthreads();
        if (c + 2 < nch) LOAD_STAGE(s, (c + 2) * 32);
    }
    #undef LOAD_STAGE

    // ---- epilogue ----
    const int g = lane >> 2, tg = lane & 3;
    #pragma unroll
    for (int mt = 0; mt < 2; mt++) {
        int r0 = rowBase + warpM * 32 + mt * 16 + g;
        int r1 = r0 + 8;
        float g0 = 0.f, g1v = 0.f;
        if (EPI == 1) { g0 = gate[r0]; g1v = gate[r1]; }
        #pragma unroll
        for (int nt = 0; nt < 8; nt++) {
            int col = colBase + warpN * 64 + nt * 8 + tg * 2;
            float d0 = acc[mt][nt][0], d1 = acc[mt][nt][1];
            float d2 = acc[mt][nt][2], d3 = acc[mt][nt][3];
            if (EPI == 0) {
                bf16* C0 = (bf16*)C0v; bf16* C1 = (bf16*)C1v;
                bf16 h0, l0, h1, l1;
                bf16_split(d0, h0, l0); bf16_split(d1, h1, l1);
                *(__nv_bfloat162*)(C0 + (size_t)r0 * ldc + col) = __nv_bfloat162(h0, h1);
                *(__nv_bfloat162*)(C1 + (size_t)r0 * ldc + col) = __nv_bfloat162(l0, l1);
                bf16_split(d2, h0, l0); bf16_split(d3, h1, l1);
                *(__nv_bfloat162*)(C0 + (size_t)r1 * ldc + col) = __nv_bfloat162(h0, h1);
                *(__nv_bfloat162*)(C1 + (size_t)r1 * ldc + col) = __nv_bfloat162(l0, l1);
            } else {
                float* C0 = (float*)C0v;
                float a0 = e0[col], a1 = e0[col + 1];
                if (EPI == 1) {
                    float p0 = e1[col], p1 = e1[col + 1];
                    *(float2*)(C0 + (size_t)r0 * ldc + col) = make_float2(d0 + a0 + g0 * p0,  d1 + a1 + g0 * p1);
                    *(float2*)(C0 + (size_t)r1 * ldc + col) = make_float2(d2 + a0 + g1v * p0, d3 + a1 + g1v * p1);
                } else {
                    *(float2*)(C0 + (size_t)r0 * ldc + col) = make_float2(d0 + a0, d1 + a1);
                    *(float2*)(C0 + (size_t)r1 * ldc + col) = make_float2(d2 + a0, d3 + a1);
                }
            }
        }
    }
}

// ---------------------------------------------------------------------------
// attend: scores -> softmax -> weights/entropy; u (bf16 split)
// ---------------------------------------------------------------------------
__global__ __launch_bounds__(256)
void attend_kernel(const float* __restrict__ ES, const float* __restrict__ r,
                   const float* __restrict__ sbias,
                   float* __restrict__ w_out, float* __restrict__ ent_out,
                   bf16* __restrict__ uh_out, bf16* __restrict__ ul_out) {
    const int b = blockIdx.x;
    const int tid = threadIdx.x;
    __shared__ float es_sh[6 * 1024];
    __shared__ float red[6][8];

    const float4* src = (const float4*)(ES + (size_t)b * 6 * 1024);
    float4* dst = (float4*)es_sh;
    #pragma unroll
    for (int i = 0; i < 6; i++) dst[tid + i * 256] = src[tid + i * 256];
    float4 rv = ((const float4*)(r + (size_t)b * 1024))[tid];
    __syncthreads();

    float4 ev[6];
    float sc[6];
    #pragma unroll
    for (int s = 0; s < 6; s++) {
        ev[s] = *(const float4*)&es_sh[s * 1024 + tid * 4];
        sc[s] = ev[s].x * rv.x + ev[s].y * rv.y + ev[s].z * rv.z + ev[s].w * rv.w;
    }
    #pragma unroll
    for (int s = 0; s < 6; s++)
        for (int o = 16; o; o >>= 1) sc[s] += __shfl_xor_sync(0xFFFFFFFFu, sc[s], o);
    if ((tid & 31) == 0) {
        #pragma unroll
        for (int s = 0; s < 6; s++) red[s][tid >> 5] = sc[s];
    }
    __syncthreads();

    float w[6], m = -1e30f;
    #pragma unroll
    for (int s = 0; s < 6; s++) {
        float t = sbias[s];
        #pragma unroll
        for (int wp = 0; wp < 8; wp++) t += red[s][wp];
        w[s] = t; m = fmaxf(m, t);
    }
    float Z = 0.f;
    #pragma unroll
    for (int s = 0; s < 6; s++) { w[s] = expf(w[s] - m); Z += w[s]; }
    float inv = 1.f / Z, ent = 0.f;
    #pragma unroll
    for (int s = 0; s < 6; s++) { w[s] *= inv; ent -= w[s] * logf(w[s] + 1e-8f); }
    if (tid == 0) {
        #pragma unroll
        for (int s = 0; s < 6; s++) w_out[(size_t)b * 6 + s] = w[s];
        ent_out[b] = ent;
    }

    float4 u;
    u.x = w[0]*ev[0].x; u.y = w[0]*ev[0].y; u.z = w[0]*ev[0].z; u.w = w[0]*ev[0].w;
    #pragma unroll
    for (int s = 1; s < 6; s++) {
        u.x += w[s]*ev[s].x; u.y += w[s]*ev[s].y; u.z += w[s]*ev[s].z; u.w += w[s]*ev[s].w;
    }
    bf16 hx, lx, hy, ly, hz, lz, hw, lw;
    bf16_split(u.x, hx, lx); bf16_split(u.y, hy, ly);
    bf16_split(u.z, hz, lz); bf16_split(u.w, hw, lw);
    size_t o = (size_t)b * 1024 + tid * 4;
    *(__nv_bfloat162*)(uh_out + o)     = __nv_bfloat162(hx, hy);
    *(__nv_bfloat162*)(uh_out + o + 2) = __nv_bfloat162(hz, hw);
    *(__nv_bfloat162*)(ul_out + o)     = __nv_bfloat162(lx, ly);
    *(__nv_bfloat162*)(ul_out + o + 2) = __nv_bfloat162(lz, lw);
}

// ---------------------------------------------------------------------------
// Host
// ---------------------------------------------------------------------------
static const int GEMM_SMEM = NSTAGE * STG * 2;   // 81920 B -> 2 CTAs/SM

extern "C" void kernel_launch(void* const* d_in, const int* in_sizes, int n_in,
                              void* d_out, int out_size) {
    const float* ES    = (const float*)d_in[0];
    const float* gate  = (const float*)d_in[2];
    const float* Wk    = (const float*)d_in[3];
    const float* Wv    = (const float*)d_in[5];
    const float* bv    = (const float*)d_in[6];
    const float* Wq    = (const float*)d_in[7];
    const float* bq    = (const float*)d_in[8];
    const float* Wp    = (const float*)d_in[9];
    const float* bp    = (const float*)d_in[10];
    const float* sbias = (const float*)d_in[11];

    const int B = in_sizes[2];    // [B,1]
    const int H = in_sizes[4];    // [H]
    const int S = in_sizes[11];   // [S]

    float* out       = (float*)d_out;
    float* out_fused = out;
    float* out_w     = out + (size_t)B * H;
    float* out_ent   = out_w + (size_t)B * S;

    bf16 *ch, *cl, *wkh, *wkl, *wqh, *wql, *wth, *wtl, *vth, *vtl, *uh, *ul;
    float *rr, *cp, *pp;
    cudaGetSymbolAddress((void**)&ch,  g_cond_hi);
    cudaGetSymbolAddress((void**)&cl,  g_cond_lo);
    cudaGetSymbolAddress((void**)&wkh, g_Wk_hi);
    cudaGetSymbolAddress((void**)&wkl, g_Wk_lo);
    cudaGetSymbolAddress((void**)&wqh, g_Wq_hi);
    cudaGetSymbolAddress((void**)&wql, g_Wq_lo);
    cudaGetSymbolAddress((void**)&wth, g_Wt_hi);
    cudaGetSymbolAddress((void**)&wtl, g_Wt_lo);
    cudaGetSymbolAddress((void**)&vth, g_WvT_hi);
    cudaGetSymbolAddress((void**)&vtl, g_WvT_lo);
    cudaGetSymbolAddress((void**)&uh,  g_u_hi);
    cudaGetSymbolAddress((void**)&ul,  g_u_lo);
    cudaGetSymbolAddress((void**)&rr,  g_r);
    cudaGetSymbolAddress((void**)&cp,  g_cp);
    cudaGetSymbolAddress((void**)&pp,  g_pp);

    cudaFuncSetAttribute(mma_gemm<0>, cudaFuncAttributeMaxDynamicSharedMemorySize, GEMM_SMEM);
    cudaFuncSetAttribute(mma_gemm<1>, cudaFuncAttributeMaxDynamicSharedMemorySize, GEMM_SMEM);
    cudaFuncSetAttribute(mma_gemm<2>, cudaFuncAttributeMaxDynamicSharedMemorySize, GEMM_SMEM);

    // 0: prep (fold + weight splits + Wv transpose-split)
    {
        int grid = (H * 32) / 256 + (H * H) / 256 + (2 * H * H) / 256 + (H / 32) * (H / 32);
        prep_kernel<<<grid, 256>>>(Wk, Wq, Wv, bq, bp, Wp,
                                   wkh, wkl, wqh, wql, vth, vtl, cp, pp, H);
    }
    // 1: pools + cond split
    pool_kernel<<<(B * H + 255) / 256, 256>>>(ES, ch, cl, B, S, H);
    // 2: K1: Wt[m,n] = sum_j Wk[m,j]*Wq[n,j]  -> [H, 2H], split epilogue
    {
        dim3 grid((2 * H) / 128, H / 128);
        mma_gemm<0><<<grid, 256, GEMM_SMEM>>>(wkh, wkl, wqh, wql,
            wth, wtl, 2 * H, H, nullptr, nullptr, nullptr);
    }
    // 3: K2: r[b,h] = sum_i cond[b,i]*Wt[h,i] + cp[h] + gate[b]*pp[h]
    {
        dim3 grid(H / 128, B / 128);
        mma_gemm<1><<<grid, 256, GEMM_SMEM>>>(ch, cl, wth, wtl,
            rr, nullptr, H, 2 * H, cp, pp, gate);
    }
    // 4: attend (softmax/entropy + u split)
    attend_kernel<<<B, 256>>>(ES, rr, sbias, out_w, out_ent, uh, ul);
    // 5: K4: fused[b,j] = sum_h u[b,h]*WvT[j,h] + bv[j]
    {
        dim3 grid(H / 128, B / 128);
        mma_gemm<2><<<grid, 256, GEMM_SMEM>>>(uh, ul, vth, vtl,
            out_fused, nullptr, H, H, bv, nullptr, nullptr);
    }
}